// round 13
// baseline (speedup 1.0000x reference)
#include <cuda_runtime.h>
#include <cuda_fp16.h>
#include <math.h>
#include <stdint.h>

#define T_SEQ 4096
#define C_DIM 2048
#define KV_DIM 512
#define QKV_N 3072
#define NH 16
#define NKV 4
#define HD 128
#define HALF 64
#define WIN 64
#define KDIM 2048
#define KT 64                 // 2048 / 32

// Scratch (no runtime allocation allowed)
__device__ float  g_Q[T_SEQ * C_DIM];
__device__ float  g_K[T_SEQ * KV_DIM];
__device__ float  g_V[T_SEQ * KV_DIM];
__device__ __half g_AOH[T_SEQ * C_DIM];        // attention output, fp16
__device__ __half g_XH[T_SEQ * C_DIM];         // x, fp16
__device__ __half g_WH[QKV_N * KDIM];          // [wq|wk|wv]^T  [N][K] fp16
__device__ __half g_WOH[C_DIM * KDIM];         // wo^T          [N][K] fp16
__device__ float2 g_RC[T_SEQ * HALF];          // rope (cos,sin) table

// ---------------------------------------------------------------------------
// One-time prep kernels
// ---------------------------------------------------------------------------
__global__ void rc_kernel() {
    int idx = blockIdx.x * blockDim.x + threadIdx.x;
    if (idx >= T_SEQ * HALF) return;
    int t = idx >> 6;
    int j = idx & 63;
    float inv = powf(10000.0f, -(float)j / (float)HALF);
    float s, c;
    sincosf((float)t * inv, &s, &c);
    g_RC[idx] = make_float2(c, s);
}

__global__ void x_to_half(const float4* __restrict__ src, int n4) {
    int i = blockIdx.x * blockDim.x + threadIdx.x;
    if (i >= n4) return;
    float4 v = src[i];
    __half2* dst = (__half2*)(g_XH + (size_t)i * 4);
    dst[0] = __floats2half2_rn(v.x, v.y);
    dst[1] = __floats2half2_rn(v.z, v.w);
}

// Transpose + convert: g_WH[n][k] = half(src[k][n]); src picked per n-region.
__global__ void build_wt(const float* __restrict__ wq, const float* __restrict__ wk,
                         const float* __restrict__ wv) {
    __shared__ float tile[32][33];
    int k0 = blockIdx.x * 32;
    int n0 = blockIdx.y * 32;
    int tx = threadIdx.x, ty = threadIdx.y;
    const float* src;
    int nb, noff;
    if (n0 < C_DIM)               { src = wq; nb = C_DIM;  noff = 0; }
    else if (n0 < C_DIM + KV_DIM) { src = wk; nb = KV_DIM; noff = C_DIM; }
    else                          { src = wv; nb = KV_DIM; noff = C_DIM + KV_DIM; }
#pragma unroll
    for (int j = 0; j < 4; j++)
        tile[ty + j * 8][tx] =
            src[(size_t)(k0 + ty + j * 8) * nb + (n0 - noff + tx)];
    __syncthreads();
#pragma unroll
    for (int j = 0; j < 4; j++)
        g_WH[(size_t)(n0 + ty + j * 8) * KDIM + k0 + tx] =
            __float2half(tile[tx][ty + j * 8]);
}

__global__ void build_wot(const float* __restrict__ wo) {
    __shared__ float tile[32][33];
    int k0 = blockIdx.x * 32;
    int n0 = blockIdx.y * 32;
    int tx = threadIdx.x, ty = threadIdx.y;
#pragma unroll
    for (int j = 0; j < 4; j++)
        tile[ty + j * 8][tx] = wo[(size_t)(k0 + ty + j * 8) * C_DIM + n0 + tx];
    __syncthreads();
#pragma unroll
    for (int j = 0; j < 4; j++)
        g_WOH[(size_t)(n0 + ty + j * 8) * KDIM + k0 + tx] =
            __float2half(tile[tx][ty + j * 8]);
}

// ---------------------------------------------------------------------------
// FP16 mma.sync GEMM, wide tile: CTA 128x256x32, 256 threads (8 warps 2x4),
// warp tile 64x64 (acc[4][8][4]), mma.m16n8k16, ldmatrix frag loads.
// K-major tiles, 40-half padded rows (conflict-free LDSM).
// cp.async 5-stage pipeline, 1 CTA/SM, no reg cap (launch_bounds(256,1)).
// mode 0: plain fp32 store. mode 1: QKV epilogue (rope + route).
// ---------------------------------------------------------------------------
#define STAGES 5
#define SROW 40                               // halves per smem row
#define A_TILE_BYTES (128 * SROW * 2)         // 10240
#define B_TILE_BYTES (256 * SROW * 2)         // 20480
#define STAGE_BYTES (A_TILE_BYTES + B_TILE_BYTES)   // 30720
#define SMEM_BYTES (STAGES * STAGE_BYTES)     // 153600

__device__ __forceinline__ void cp16(uint32_t dst, const __half* src) {
    asm volatile("cp.async.cg.shared.global [%0], [%1], 16;\n" :: "r"(dst), "l"(src));
}

#define LDSM4(r0, r1, r2, r3, addr)                                            \
    asm volatile("ldmatrix.sync.aligned.m8n8.x4.shared.b16 {%0,%1,%2,%3}, [%4];" \
                 : "=r"(r0), "=r"(r1), "=r"(r2), "=r"(r3) : "r"(addr))

__device__ __forceinline__ void mma_f16(float c[4], const uint32_t a[4],
                                        const uint32_t b[2]) {
    asm volatile(
        "mma.sync.aligned.m16n8k16.row.col.f32.f16.f16.f32 "
        "{%0,%1,%2,%3}, {%4,%5,%6,%7}, {%8,%9}, {%0,%1,%2,%3};\n"
        : "+f"(c[0]), "+f"(c[1]), "+f"(c[2]), "+f"(c[3])
        : "r"(a[0]), "r"(a[1]), "r"(a[2]), "r"(a[3]), "r"(b[0]), "r"(b[1]));
}

__device__ __forceinline__ void qkv_store(int t, int col, float v0, float v1) {
    if (col < C_DIM) {
        int jj = (col & 127) >> 1;
        float2 cs = g_RC[t * HALF + jj];
        *(float2*)&g_Q[(size_t)t * C_DIM + col] =
            make_float2(v0 * cs.x - v1 * cs.y, v0 * cs.y + v1 * cs.x);
    } else if (col < C_DIM + KV_DIM) {
        int kc = col - C_DIM;
        int jj = (kc & 127) >> 1;
        float2 cs = g_RC[t * HALF + jj];
        *(float2*)&g_K[(size_t)t * KV_DIM + kc] =
            make_float2(v0 * cs.x - v1 * cs.y, v0 * cs.y + v1 * cs.x);
    } else {
        int vc = col - C_DIM - KV_DIM;
        *(float2*)&g_V[(size_t)t * KV_DIM + vc] = make_float2(v0, v1);
    }
}

__global__ void __launch_bounds__(256, 1) gemm_f16(const __half* __restrict__ A,
                                                   const __half* __restrict__ Bt,
                                                   float* __restrict__ C,
                                                   int N, int mode) {
    extern __shared__ char smem[];
    uint32_t smem_u;
    asm("{.reg .u64 t; cvta.to.shared.u64 t, %1; cvt.u32.u64 %0, t;}"
        : "=r"(smem_u) : "l"(smem));

    const int tid = threadIdx.x;
    const int bm = blockIdx.y * 128;
    const int bn = blockIdx.x * 256;
    const int warp = tid >> 5;
    const int lane = tid & 31;
    const int wm = warp >> 2;     // 0..1
    const int wn = warp & 3;      // 0..3
    const int g  = lane >> 2;     // 0..7
    const int tg = lane & 3;      // 0..3

    // ldmatrix per-lane address constants (byte offsets within stage)
    const int mi = lane >> 3;     // matrix index 0..3
    const int rw = lane & 7;      // row within matrix
    // A: m0=rows0-7/k0-7, m1=rows8-15/k0-7, m2=rows0-7/k8-15, m3=rows8-15/k8-15
    const uint32_t aoff0 =
        (uint32_t)(((wm * 64 + ((mi & 1) << 3) + rw) * SROW + ((mi >> 1) << 3)) * 2);
    // B: m0=(j,k0-7), m1=(j,k8-15), m2=(j+1,k0-7), m3=(j+1,k8-15)
    const uint32_t boff0 =
        (uint32_t)(((wn * 64 + ((mi >> 1) << 3) + rw) * SROW + ((mi & 1) << 3)) * 2) +
        A_TILE_BYTES;

    // loader mapping: A 512 chunks (2/thread), B 1024 chunks (4/thread)
    const int lrow = tid >> 2;    // 0..63
    const int ch   = tid & 3;
    const __half* ap = A + (size_t)(bm + lrow) * KDIM + ch * 8;
    const __half* bp = Bt + (size_t)(bn + lrow) * KDIM + ch * 8;
    const uint32_t aoffs = (uint32_t)((lrow * SROW + ch * 8) * 2);
    const uint32_t boffs = aoffs + A_TILE_BYTES;

    float acc[4][8][4];
#pragma unroll
    for (int i = 0; i < 4; i++)
#pragma unroll
        for (int j = 0; j < 8; j++)
#pragma unroll
            for (int r = 0; r < 4; r++) acc[i][j][r] = 0.f;

    // prologue: stages 0..STAGES-2
#pragma unroll
    for (int s = 0; s < STAGES - 1; s++) {
        uint32_t base = smem_u + (uint32_t)s * STAGE_BYTES;
        cp16(base + aoffs, ap);
        cp16(base + aoffs + 64 * SROW * 2, ap + (size_t)64 * KDIM);
#pragma unroll
        for (int p = 0; p < 4; p++)
            cp16(base + boffs + p * (64 * SROW * 2), bp + (size_t)(64 * p) * KDIM);
        asm volatile("cp.async.commit_group;\n" ::);
        ap += 32;
        bp += 32;
    }

    int st = 0;
    int wst = STAGES - 1;
    for (int kt = 0; kt < KT; kt++) {
        // wait: stage kt's group must be complete (N = min(STAGES-2, KT-1-kt))
        if (kt < KT - 3)
            asm volatile("cp.async.wait_group 3;\n" ::);
        else if (kt == KT - 3)
            asm volatile("cp.async.wait_group 2;\n" ::);
        else if (kt == KT - 2)
            asm volatile("cp.async.wait_group 1;\n" ::);
        else
            asm volatile("cp.async.wait_group 0;\n" ::);
        __syncthreads();

        if (kt + STAGES - 1 < KT) {
            uint32_t base = smem_u + (uint32_t)wst * STAGE_BYTES;
            cp16(base + aoffs, ap);
            cp16(base + aoffs + 64 * SROW * 2, ap + (size_t)64 * KDIM);
#pragma unroll
            for (int p = 0; p < 4; p++)
                cp16(base + boffs + p * (64 * SROW * 2),
                     bp + (size_t)(64 * p) * KDIM);
            asm volatile("cp.async.commit_group;\n" ::);
            ap += 32;
            bp += 32;
            wst = (wst == STAGES - 1) ? 0 : wst + 1;
        }

        const uint32_t sbase = smem_u + (uint32_t)st * STAGE_BYTES;
        st = (st == STAGES - 1) ? 0 : st + 1;

#pragma unroll
        for (int s = 0; s < 2; s++) {       // two k16 steps per k-tile
            uint32_t af[4][4], bf[8][2];
#pragma unroll
            for (int i = 0; i < 4; i++)
                LDSM4(af[i][0], af[i][1], af[i][2], af[i][3],
                      sbase + aoff0 + (uint32_t)(i * 16 * SROW * 2 + s * 32));
#pragma unroll
            for (int jp = 0; jp < 4; jp++)
                LDSM4(bf[jp * 2][0], bf[jp * 2][1], bf[jp * 2 + 1][0],
                      bf[jp * 2 + 1][1],
                      sbase + boff0 + (uint32_t)(jp * 16 * SROW * 2 + s * 32));
#pragma unroll
            for (int i = 0; i < 4; i++)
#pragma unroll
                for (int j = 0; j < 8; j++) mma_f16(acc[i][j], af[i], bf[j]);
        }
    }

    if (mode == 0) {
#pragma unroll
        for (int i = 0; i < 4; i++)
#pragma unroll
            for (int j = 0; j < 8; j++) {
                int row = bm + wm * 64 + i * 16 + g;
                int col = bn + wn * 64 + j * 8 + 2 * tg;
                *(float2*)(C + (size_t)row * N + col) =
                    make_float2(acc[i][j][0], acc[i][j][1]);
                *(float2*)(C + (size_t)(row + 8) * N + col) =
                    make_float2(acc[i][j][2], acc[i][j][3]);
            }
    } else {
#pragma unroll
        for (int i = 0; i < 4; i++)
#pragma unroll
            for (int j = 0; j < 8; j++) {
                int row = bm + wm * 64 + i * 16 + g;
                int col = bn + wn * 64 + j * 8 + 2 * tg;
                qkv_store(row, col, acc[i][j][0], acc[i][j][1]);
                qkv_store(row + 8, col, acc[i][j][2], acc[i][j][3]);
            }
    }
}

// ---------------------------------------------------------------------------
// Sliding-window attention: one warp handles 4 adjacent queries of one head,
// sharing each K/V float4 load. Branchy online softmax. sink cancels; ignored.
// Output written as fp16 (feeds final GEMM directly).
// ---------------------------------------------------------------------------
__global__ void __launch_bounds__(256) attn_kernel(const float* __restrict__ Q,
                                                   const float* __restrict__ K,
                                                   const float* __restrict__ V) {
    const int warp = threadIdx.x >> 5;
    const int lane = threadIdx.x & 31;
    const int tq = (blockIdx.x * 8 + warp) * 4;
    const int h = blockIdx.y;
    const int kh = h >> 2;
    const float scale = 0.08838834764831845f;

    float4 q[4];
#pragma unroll
    for (int i = 0; i < 4; i++)
        q[i] = *(const float4*)(Q + (size_t)(tq + i) * C_DIM + h * HD + lane * 4);

    float m[4] = {-1e30f, -1e30f, -1e30f, -1e30f};
    float l[4] = {0.f, 0.f, 0.f, 0.f};
    float4 a[4];
#pragma unroll
    for (int i = 0; i < 4; i++) a[i] = make_float4(0.f, 0.f, 0.f, 0.f);

    int s0 = tq - WIN;      if (s0 < 0) s0 = 0;
    int s1 = tq + 3 + WIN;  if (s1 > T_SEQ - 1) s1 = T_SEQ - 1;

    for (int s = s0; s <= s1; s++) {
        float4 kv = *(const float4*)(K + (size_t)s * KV_DIM + kh * HD + lane * 4);
        float4 vv = *(const float4*)(V + (size_t)s * KV_DIM + kh * HD + lane * 4);
#pragma unroll
        for (int i = 0; i < 4; i++) {
            int t = tq + i;
            if (s < t - WIN || s > t + WIN) continue;  // warp-uniform
            float d = q[i].x * kv.x + q[i].y * kv.y + q[i].z * kv.z + q[i].w * kv.w;
#pragma unroll
            for (int o = 16; o > 0; o >>= 1) d += __shfl_xor_sync(0xffffffffu, d, o);
            d *= scale;
            if (d <= m[i]) {
                float p = __expf(d - m[i]);
                l[i] += p;
                a[i].x += p * vv.x;
                a[i].y += p * vv.y;
                a[i].z += p * vv.z;
                a[i].w += p * vv.w;
            } else {
                float corr = __expf(m[i] - d);
                m[i] = d;
                l[i] = l[i] * corr + 1.f;
                a[i].x = a[i].x * corr + vv.x;
                a[i].y = a[i].y * corr + vv.y;
                a[i].z = a[i].z * corr + vv.z;
                a[i].w = a[i].w * corr + vv.w;
            }
        }
    }
#pragma unroll
    for (int i = 0; i < 4; i++) {
        float inv = 1.f / l[i];
        __half2* ao = (__half2*)(g_AOH + (size_t)(tq + i) * C_DIM + h * HD + lane * 4);
        ao[0] = __floats2half2_rn(a[i].x * inv, a[i].y * inv);
        ao[1] = __floats2half2_rn(a[i].z * inv, a[i].w * inv);
    }
}

// ---------------------------------------------------------------------------
extern "C" void kernel_launch(void* const* d_in, const int* in_sizes, int n_in,
                              void* d_out, int out_size) {
    const float* x  = (const float*)d_in[0];
    const float* wq = (const float*)d_in[1];
    const float* wk = (const float*)d_in[2];
    const float* wv = (const float*)d_in[3];
    const float* wo = (const float*)d_in[4];
    // d_in[5] = sink: constant per softmax row -> cancels; ignored.
    float* out = (float*)d_out;

    float *Q, *Kp, *Vp;
    __half *XH, *WH, *WOH, *AOH;
    cudaGetSymbolAddress((void**)&Q,   g_Q);
    cudaGetSymbolAddress((void**)&Kp,  g_K);
    cudaGetSymbolAddress((void**)&Vp,  g_V);
    cudaGetSymbolAddress((void**)&XH,  g_XH);
    cudaGetSymbolAddress((void**)&WH,  g_WH);
    cudaGetSymbolAddress((void**)&WOH, g_WOH);
    cudaGetSymbolAddress((void**)&AOH, g_AOH);

    // one-time prep: rope table, fp16 conversions, weight transposes
    rc_kernel<<<(T_SEQ * HALF + 255) / 256, 256>>>();
    {
        int n4 = T_SEQ * C_DIM / 4;
        x_to_half<<<(n4 + 255) / 256, 256>>>((const float4*)x, n4);
        build_wt<<<dim3(KDIM / 32, QKV_N / 32), dim3(32, 8)>>>(wq, wk, wv);
        build_wot<<<dim3(KDIM / 32, C_DIM / 32), dim3(32, 8)>>>(wo);
    }

    cudaFuncSetAttribute(gemm_f16, cudaFuncAttributeMaxDynamicSharedMemorySize,
                         SMEM_BYTES);
    cudaFuncSetAttribute(gemm_f16, cudaFuncAttributePreferredSharedMemoryCarveout,
                         100);

    // QKV projection (fused, rope in epilogue)
    gemm_f16<<<dim3(QKV_N / 256, T_SEQ / 128), 256, SMEM_BYTES>>>(XH, WH, nullptr,
                                                                  QKV_N, 1);

    attn_kernel<<<dim3(T_SEQ / 32, NH), 256>>>(Q, Kp, Vp);

    // output projection
    gemm_f16<<<dim3(C_DIM / 256, T_SEQ / 128), 256, SMEM_BYTES>>>(AOH, WOH, out,
                                                                  C_DIM, 0);
}

// round 14
// speedup vs baseline: 2.2425x; 2.2425x over previous
#include <cuda_runtime.h>
#include <cuda_fp16.h>
#include <math.h>
#include <stdint.h>

#define T_SEQ 4096
#define C_DIM 2048
#define KV_DIM 512
#define QKV_N 3072
#define NH 16
#define NKV 4
#define HD 128
#define HALF 64
#define WIN 64
#define KDIM 2048
#define KT 64                 // 2048 / 32

// Scratch (no runtime allocation allowed)
__device__ __half g_QH[T_SEQ * C_DIM];         // Q (roped), fp16
__device__ __half g_KH[T_SEQ * KV_DIM];        // K (roped), fp16
__device__ __half g_VH[T_SEQ * KV_DIM];        // V, fp16
__device__ __half g_AOH[T_SEQ * C_DIM];        // attention output, fp16
__device__ __half g_XH[T_SEQ * C_DIM];         // x, fp16
__device__ __half g_WH[QKV_N * KDIM];          // [wq|wk|wv]^T  [N][K] fp16
__device__ __half g_WOH[C_DIM * KDIM];         // wo^T          [N][K] fp16
__device__ float2 g_RC[T_SEQ * HALF];          // rope (cos,sin) table

// ---------------------------------------------------------------------------
// One-time prep kernels
// ---------------------------------------------------------------------------
__global__ void rc_kernel() {
    int idx = blockIdx.x * blockDim.x + threadIdx.x;
    if (idx >= T_SEQ * HALF) return;
    int t = idx >> 6;
    int j = idx & 63;
    float inv = powf(10000.0f, -(float)j / (float)HALF);
    float s, c;
    sincosf((float)t * inv, &s, &c);
    g_RC[idx] = make_float2(c, s);
}

__global__ void x_to_half(const float4* __restrict__ src, int n4) {
    int i = blockIdx.x * blockDim.x + threadIdx.x;
    if (i >= n4) return;
    float4 v = src[i];
    __half2* dst = (__half2*)(g_XH + (size_t)i * 4);
    dst[0] = __floats2half2_rn(v.x, v.y);
    dst[1] = __floats2half2_rn(v.z, v.w);
}

// Transpose + convert: g_WH[n][k] = half(src[k][n]); src picked per n-region.
__global__ void build_wt(const float* __restrict__ wq, const float* __restrict__ wk,
                         const float* __restrict__ wv) {
    __shared__ float tile[32][33];
    int k0 = blockIdx.x * 32;
    int n0 = blockIdx.y * 32;
    int tx = threadIdx.x, ty = threadIdx.y;
    const float* src;
    int nb, noff;
    if (n0 < C_DIM)               { src = wq; nb = C_DIM;  noff = 0; }
    else if (n0 < C_DIM + KV_DIM) { src = wk; nb = KV_DIM; noff = C_DIM; }
    else                          { src = wv; nb = KV_DIM; noff = C_DIM + KV_DIM; }
#pragma unroll
    for (int j = 0; j < 4; j++)
        tile[ty + j * 8][tx] =
            src[(size_t)(k0 + ty + j * 8) * nb + (n0 - noff + tx)];
    __syncthreads();
#pragma unroll
    for (int j = 0; j < 4; j++)
        g_WH[(size_t)(n0 + ty + j * 8) * KDIM + k0 + tx] =
            __float2half(tile[tx][ty + j * 8]);
}

__global__ void build_wot(const float* __restrict__ wo) {
    __shared__ float tile[32][33];
    int k0 = blockIdx.x * 32;
    int n0 = blockIdx.y * 32;
    int tx = threadIdx.x, ty = threadIdx.y;
#pragma unroll
    for (int j = 0; j < 4; j++)
        tile[ty + j * 8][tx] = wo[(size_t)(k0 + ty + j * 8) * C_DIM + n0 + tx];
    __syncthreads();
#pragma unroll
    for (int j = 0; j < 4; j++)
        g_WOH[(size_t)(n0 + ty + j * 8) * KDIM + k0 + tx] =
            __float2half(tile[tx][ty + j * 8]);
}

// ---------------------------------------------------------------------------
// Shared MMA helpers
// ---------------------------------------------------------------------------
__device__ __forceinline__ void cp16(uint32_t dst, const __half* src) {
    asm volatile("cp.async.cg.shared.global [%0], [%1], 16;\n" :: "r"(dst), "l"(src));
}

#define LDSM4(r0, r1, r2, r3, addr)                                            \
    asm volatile("ldmatrix.sync.aligned.m8n8.x4.shared.b16 {%0,%1,%2,%3}, [%4];" \
                 : "=r"(r0), "=r"(r1), "=r"(r2), "=r"(r3) : "r"(addr))

#define LDSM4T(r0, r1, r2, r3, addr)                                           \
    asm volatile(                                                              \
        "ldmatrix.sync.aligned.m8n8.x4.trans.shared.b16 {%0,%1,%2,%3}, [%4];"  \
        : "=r"(r0), "=r"(r1), "=r"(r2), "=r"(r3) : "r"(addr))

__device__ __forceinline__ void mma_f16(float c[4], const uint32_t a[4],
                                        const uint32_t b[2]) {
    asm volatile(
        "mma.sync.aligned.m16n8k16.row.col.f32.f16.f16.f32 "
        "{%0,%1,%2,%3}, {%4,%5,%6,%7}, {%8,%9}, {%0,%1,%2,%3};\n"
        : "+f"(c[0]), "+f"(c[1]), "+f"(c[2]), "+f"(c[3])
        : "r"(a[0]), "r"(a[1]), "r"(a[2]), "r"(a[3]), "r"(b[0]), "r"(b[1]));
}

// ---------------------------------------------------------------------------
// FP16 mma.sync GEMM (round-10 config): CTA 128x128x32, 256 threads (2x4
// warps), warp tile 64x32, ldmatrix frags, K-major 40-half padded rows,
// cp.async 5-stage, 2 CTAs/SM.
// mode 0: plain fp32 store. mode 1: QKV epilogue (rope + route, fp16 out).
// ---------------------------------------------------------------------------
#define STAGES 5
#define SROW 40                               // halves per smem row
#define TILE_BYTES (128 * SROW * 2)           // 10240
#define STAGE_BYTES (2 * TILE_BYTES)          // 20480
#define SMEM_BYTES (STAGES * STAGE_BYTES)     // 102400

__device__ __forceinline__ void qkv_store(int t, int col, float v0, float v1) {
    if (col < C_DIM) {
        int jj = (col & 127) >> 1;
        float2 cs = g_RC[t * HALF + jj];
        *(__half2*)&g_QH[(size_t)t * C_DIM + col] =
            __floats2half2_rn(v0 * cs.x - v1 * cs.y, v0 * cs.y + v1 * cs.x);
    } else if (col < C_DIM + KV_DIM) {
        int kc = col - C_DIM;
        int jj = (kc & 127) >> 1;
        float2 cs = g_RC[t * HALF + jj];
        *(__half2*)&g_KH[(size_t)t * KV_DIM + kc] =
            __floats2half2_rn(v0 * cs.x - v1 * cs.y, v0 * cs.y + v1 * cs.x);
    } else {
        int vc = col - C_DIM - KV_DIM;
        *(__half2*)&g_VH[(size_t)t * KV_DIM + vc] = __floats2half2_rn(v0, v1);
    }
}

__global__ void __launch_bounds__(256, 2) gemm_f16(const __half* __restrict__ A,
                                                   const __half* __restrict__ Bt,
                                                   float* __restrict__ C,
                                                   int N, int mode) {
    extern __shared__ char smem[];
    uint32_t smem_u;
    asm("{.reg .u64 t; cvta.to.shared.u64 t, %1; cvt.u32.u64 %0, t;}"
        : "=r"(smem_u) : "l"(smem));

    const int tid = threadIdx.x;
    const int bm = blockIdx.y * 128;
    const int bn = blockIdx.x * 128;
    const int warp = tid >> 5;
    const int lane = tid & 31;
    const int wm = warp >> 2;
    const int wn = warp & 3;
    const int g  = lane >> 2;
    const int tg = lane & 3;

    const int mi = lane >> 3;
    const int rw = lane & 7;
    const uint32_t aoff0 =
        (uint32_t)(((wm * 64 + ((mi & 1) << 3) + rw) * SROW + ((mi >> 1) << 3)) * 2);
    const uint32_t boff0 =
        (uint32_t)(((wn * 32 + ((mi >> 1) << 3) + rw) * SROW + ((mi & 1) << 3)) * 2) +
        TILE_BYTES;

    const int row4 = tid >> 2;
    const int ch   = tid & 3;
    const __half* ap = A + (size_t)(bm + row4) * KDIM + ch * 8;
    const __half* bp = Bt + (size_t)(bn + row4) * KDIM + ch * 8;
    const uint32_t soff = (uint32_t)((row4 * SROW + ch * 8) * 2);

    float acc[4][4][4];
#pragma unroll
    for (int i = 0; i < 4; i++)
#pragma unroll
        for (int j = 0; j < 4; j++)
#pragma unroll
            for (int r = 0; r < 4; r++) acc[i][j][r] = 0.f;

#pragma unroll
    for (int s = 0; s < STAGES - 1; s++) {
        uint32_t base = smem_u + (uint32_t)s * STAGE_BYTES;
        cp16(base + soff, ap);
        cp16(base + soff + 64 * SROW * 2, ap + (size_t)64 * KDIM);
        cp16(base + TILE_BYTES + soff, bp);
        cp16(base + TILE_BYTES + soff + 64 * SROW * 2, bp + (size_t)64 * KDIM);
        asm volatile("cp.async.commit_group;\n" ::);
        ap += 32;
        bp += 32;
    }

    int st = 0;
    int wst = STAGES - 1;
    for (int kt = 0; kt < KT; kt++) {
        if (kt < KT - 3)
            asm volatile("cp.async.wait_group 3;\n" ::);
        else if (kt == KT - 3)
            asm volatile("cp.async.wait_group 2;\n" ::);
        else if (kt == KT - 2)
            asm volatile("cp.async.wait_group 1;\n" ::);
        else
            asm volatile("cp.async.wait_group 0;\n" ::);
        __syncthreads();

        if (kt + STAGES - 1 < KT) {
            uint32_t base = smem_u + (uint32_t)wst * STAGE_BYTES;
            cp16(base + soff, ap);
            cp16(base + soff + 64 * SROW * 2, ap + (size_t)64 * KDIM);
            cp16(base + TILE_BYTES + soff, bp);
            cp16(base + TILE_BYTES + soff + 64 * SROW * 2, bp + (size_t)64 * KDIM);
            asm volatile("cp.async.commit_group;\n" ::);
            ap += 32;
            bp += 32;
            wst = (wst == STAGES - 1) ? 0 : wst + 1;
        }

        const uint32_t sbase = smem_u + (uint32_t)st * STAGE_BYTES;
        st = (st == STAGES - 1) ? 0 : st + 1;

#pragma unroll
        for (int s = 0; s < 2; s++) {
            uint32_t af[4][4], bf[4][2];
#pragma unroll
            for (int i = 0; i < 4; i++)
                LDSM4(af[i][0], af[i][1], af[i][2], af[i][3],
                      sbase + aoff0 + (uint32_t)(i * 16 * SROW * 2 + s * 32));
#pragma unroll
            for (int jp = 0; jp < 2; jp++)
                LDSM4(bf[jp * 2][0], bf[jp * 2][1], bf[jp * 2 + 1][0],
                      bf[jp * 2 + 1][1],
                      sbase + boff0 + (uint32_t)(jp * 16 * SROW * 2 + s * 32));
#pragma unroll
            for (int i = 0; i < 4; i++)
#pragma unroll
                for (int j = 0; j < 4; j++) mma_f16(acc[i][j], af[i], bf[j]);
        }
    }

    if (mode == 0) {
#pragma unroll
        for (int i = 0; i < 4; i++)
#pragma unroll
            for (int j = 0; j < 4; j++) {
                int row = bm + wm * 64 + i * 16 + g;
                int col = bn + wn * 32 + j * 8 + 2 * tg;
                *(float2*)(C + (size_t)row * N + col) =
                    make_float2(acc[i][j][0], acc[i][j][1]);
                *(float2*)(C + (size_t)(row + 8) * N + col) =
                    make_float2(acc[i][j][2], acc[i][j][3]);
            }
    } else {
#pragma unroll
        for (int i = 0; i < 4; i++)
#pragma unroll
            for (int j = 0; j < 4; j++) {
                int row = bm + wm * 64 + i * 16 + g;
                int col = bn + wn * 32 + j * 8 + 2 * tg;
                qkv_store(row, col, acc[i][j][0], acc[i][j][1]);
                qkv_store(row + 8, col, acc[i][j][2], acc[i][j][3]);
            }
    }
}

// ---------------------------------------------------------------------------
// Flash-attention block kernel. CTA = (128 queries, 1 head), 256 threads.
// Key window = 256 rows [t0-64, t0+191]. S = Q@K^T (fp16 MMA, fp32 acc),
// band+bounds mask, softmax with cross-warp smem reduction, P staged fp16 in
// smem (over dead K region), O = P@V via ldmatrix.trans for V^T.
// Band mask in local coords: col in [row, row+128].
// ---------------------------------------------------------------------------
#define QROW 136                              // Q/K/V smem row, halves
#define PROW 264                              // P smem row, halves
#define OFF_Q 0
#define OFF_K 34816                           // 128*136*2
#define OFF_V 104448                          // OFF_K + 256*136*2
#define OFF_RED 174080                        // OFF_V + 256*136*2
#define FA_SMEM (OFF_RED + 4096)              // + pmax/psum (2KB each)

__global__ void __launch_bounds__(256, 1) fa_kernel(const __half* __restrict__ QH,
                                                    const __half* __restrict__ KH,
                                                    const __half* __restrict__ VH) {
    extern __shared__ char smem[];
    uint32_t su;
    asm("{.reg .u64 t; cvta.to.shared.u64 t, %1; cvt.u32.u64 %0, t;}"
        : "=r"(su) : "l"(smem));
    float* pmaxs = (float*)(smem + OFF_RED);          // [4][128]
    float* psums = (float*)(smem + OFF_RED + 2048);   // [4][128]

    const int tid = threadIdx.x;
    const int t0 = blockIdx.x * 128;
    const int h = blockIdx.y;
    const int kh = h >> 2;
    const int warp = tid >> 5;
    const int lane = tid & 31;
    const int wm = warp >> 2;     // 0..1
    const int wn = warp & 3;      // 0..3
    const int g  = lane >> 2;
    const int tg = lane & 3;
    const int mi = lane >> 3;
    const int rw = lane & 7;
    const float scale = 0.08838834764831845f;  // 128^-0.5

    // ---- load Q (128x128) and K/V (256x128) fp16 tiles ----
    for (int c = tid; c < 2048; c += 256) {
        int row = c >> 4, o = c & 15;
        cp16(su + OFF_Q + row * (QROW * 2) + o * 16,
             QH + (size_t)(t0 + row) * C_DIM + h * HD + o * 8);
    }
    for (int c = tid; c < 4096; c += 256) {
        int row = c >> 4, o = c & 15;
        int s = t0 - 64 + row;
        uint32_t dk = su + OFF_K + row * (QROW * 2) + o * 16;
        uint32_t dv = su + OFF_V + row * (QROW * 2) + o * 16;
        if (s >= 0 && s < T_SEQ) {
            cp16(dk, KH + (size_t)s * KV_DIM + kh * HD + o * 8);
            cp16(dv, VH + (size_t)s * KV_DIM + kh * HD + o * 8);
        } else {
            *(uint4*)(smem + OFF_K + row * (QROW * 2) + o * 16) =
                make_uint4(0, 0, 0, 0);
            *(uint4*)(smem + OFF_V + row * (QROW * 2) + o * 16) =
                make_uint4(0, 0, 0, 0);
        }
    }
    asm volatile("cp.async.commit_group;\n" ::);
    asm volatile("cp.async.wait_group 0;\n" ::);
    __syncthreads();

    // ---- S = Q @ K^T : m=128 (2 wm x 64), n=256 (4 wn x 64), k=128 ----
    const uint32_t aoffQ =
        su + OFF_Q +
        (uint32_t)(((wm * 64 + ((mi & 1) << 3) + rw) * QROW + ((mi >> 1) << 3)) * 2);
    const uint32_t boffK =
        su + OFF_K +
        (uint32_t)(((wn * 64 + ((mi >> 1) << 3) + rw) * QROW + ((mi & 1) << 3)) * 2);

    float acc[4][8][4];
#pragma unroll
    for (int i = 0; i < 4; i++)
#pragma unroll
        for (int j = 0; j < 8; j++)
#pragma unroll
            for (int r = 0; r < 4; r++) acc[i][j][r] = 0.f;

#pragma unroll
    for (int s = 0; s < 8; s++) {       // 8 k16 steps (k=128)
        uint32_t af[4][4], bf[8][2];
#pragma unroll
        for (int i = 0; i < 4; i++)
            LDSM4(af[i][0], af[i][1], af[i][2], af[i][3],
                  aoffQ + (uint32_t)(i * 16 * QROW * 2 + s * 32));
#pragma unroll
        for (int jp = 0; jp < 4; jp++)
            LDSM4(bf[jp * 2][0], bf[jp * 2][1], bf[jp * 2 + 1][0],
                  bf[jp * 2 + 1][1],
                  boffK + (uint32_t)(jp * 16 * QROW * 2 + s * 32));
#pragma unroll
        for (int i = 0; i < 4; i++)
#pragma unroll
            for (int j = 0; j < 8; j++) mma_f16(acc[i][j], af[i], bf[j]);
    }

    // ---- mask + scale + per-row max (warp-partial) ----
#pragma unroll
    for (int i = 0; i < 4; i++) {
#pragma unroll
        for (int rh = 0; rh < 2; rh++) {
            int row = wm * 64 + i * 16 + g + rh * 8;
            float mx = -1e30f;
#pragma unroll
            for (int j = 0; j < 8; j++) {
#pragma unroll
                for (int rr = 0; rr < 2; rr++) {
                    int r = rh * 2 + rr;
                    int col = wn * 64 + j * 8 + 2 * tg + rr;
                    int sK = t0 - 64 + col;
                    bool val = (col >= row) && (col <= row + 128) &&
                               (sK >= 0) && (sK < T_SEQ);
                    float v = val ? acc[i][j][r] * scale : -1e30f;
                    acc[i][j][r] = v;
                    mx = fmaxf(mx, v);
                }
            }
            mx = fmaxf(mx, __shfl_xor_sync(0xffffffffu, mx, 1));
            mx = fmaxf(mx, __shfl_xor_sync(0xffffffffu, mx, 2));
            if (tg == 0) pmaxs[wn * 128 + row] = mx;
        }
    }
    __syncthreads();   // all warps done reading K; pmax complete

    // ---- exp + P (fp16, over K region) + per-row sum ----
#pragma unroll
    for (int i = 0; i < 4; i++) {
#pragma unroll
        for (int rh = 0; rh < 2; rh++) {
            int row = wm * 64 + i * 16 + g + rh * 8;
            float mrow = fmaxf(fmaxf(pmaxs[row], pmaxs[128 + row]),
                               fmaxf(pmaxs[256 + row], pmaxs[384 + row]));
            float sm = 0.f;
#pragma unroll
            for (int j = 0; j < 8; j++) {
                int r = rh * 2;
                float v0 = acc[i][j][r], v1 = acc[i][j][r + 1];
                float p0 = (v0 > -1e29f) ? __expf(v0 - mrow) : 0.f;
                float p1 = (v1 > -1e29f) ? __expf(v1 - mrow) : 0.f;
                sm += p0 + p1;
                int col = wn * 64 + j * 8 + 2 * tg;
                *(__half2*)(smem + OFF_K + row * (PROW * 2) + col * 2) =
                    __floats2half2_rn(p0, p1);
            }
            sm += __shfl_xor_sync(0xffffffffu, sm, 1);
            sm += __shfl_xor_sync(0xffffffffu, sm, 2);
            if (tg == 0) psums[wn * 128 + row] = sm;
        }
    }
    __syncthreads();   // P + psums complete

    // ---- O = P @ V : m=128, n=128 (4 wn x 32), k=256 ----
    const uint32_t aoffP =
        su + OFF_K +
        (uint32_t)(((wm * 64 + ((mi & 1) << 3) + rw) * PROW + ((mi >> 1) << 3)) * 2);
    const uint32_t voff =
        su + OFF_V +
        (uint32_t)((((mi & 1) * 8 + rw) * QROW + wn * 32 + ((mi >> 1) << 3)) * 2);

    float oacc[4][4][4];
#pragma unroll
    for (int i = 0; i < 4; i++)
#pragma unroll
        for (int j = 0; j < 4; j++)
#pragma unroll
            for (int r = 0; r < 4; r++) oacc[i][j][r] = 0.f;

#pragma unroll
    for (int ks = 0; ks < 16; ks++) {   // 16 k16 steps (k=256)
        uint32_t af[4][4], bf[4][2];
#pragma unroll
        for (int i = 0; i < 4; i++)
            LDSM4(af[i][0], af[i][1], af[i][2], af[i][3],
                  aoffP + (uint32_t)(i * 16 * PROW * 2 + ks * 32));
        LDSM4T(bf[0][0], bf[0][1], bf[1][0], bf[1][1],
               voff + (uint32_t)(ks * 16 * QROW * 2));
        LDSM4T(bf[2][0], bf[2][1], bf[3][0], bf[3][1],
               voff + 32 + (uint32_t)(ks * 16 * QROW * 2));
#pragma unroll
        for (int i = 0; i < 4; i++)
#pragma unroll
            for (int j = 0; j < 4; j++) mma_f16(oacc[i][j], af[i], bf[j]);
    }

    // ---- normalize + store fp16 ----
#pragma unroll
    for (int i = 0; i < 4; i++) {
        float li[2];
#pragma unroll
        for (int rh = 0; rh < 2; rh++) {
            int row = wm * 64 + i * 16 + g + rh * 8;
            float l = psums[row] + psums[128 + row] + psums[256 + row] +
                      psums[384 + row];
            li[rh] = 1.f / l;
        }
#pragma unroll
        for (int j = 0; j < 4; j++) {
            int row = wm * 64 + i * 16 + g;
            int col = wn * 32 + j * 8 + 2 * tg;
            *(__half2*)(g_AOH + (size_t)(t0 + row) * C_DIM + h * HD + col) =
                __floats2half2_rn(oacc[i][j][0] * li[0], oacc[i][j][1] * li[0]);
            *(__half2*)(g_AOH + (size_t)(t0 + row + 8) * C_DIM + h * HD + col) =
                __floats2half2_rn(oacc[i][j][2] * li[1], oacc[i][j][3] * li[1]);
        }
    }
}

// ---------------------------------------------------------------------------
extern "C" void kernel_launch(void* const* d_in, const int* in_sizes, int n_in,
                              void* d_out, int out_size) {
    const float* x  = (const float*)d_in[0];
    const float* wq = (const float*)d_in[1];
    const float* wk = (const float*)d_in[2];
    const float* wv = (const float*)d_in[3];
    const float* wo = (const float*)d_in[4];
    // d_in[5] = sink: constant per softmax row -> cancels; ignored.
    float* out = (float*)d_out;

    __half *QH, *KH, *VH, *XH, *WH, *WOH, *AOH;
    cudaGetSymbolAddress((void**)&QH,  g_QH);
    cudaGetSymbolAddress((void**)&KH,  g_KH);
    cudaGetSymbolAddress((void**)&VH,  g_VH);
    cudaGetSymbolAddress((void**)&XH,  g_XH);
    cudaGetSymbolAddress((void**)&WH,  g_WH);
    cudaGetSymbolAddress((void**)&WOH, g_WOH);
    cudaGetSymbolAddress((void**)&AOH, g_AOH);

    // one-time prep: rope table, fp16 conversions, weight transposes
    rc_kernel<<<(T_SEQ * HALF + 255) / 256, 256>>>();
    {
        int n4 = T_SEQ * C_DIM / 4;
        x_to_half<<<(n4 + 255) / 256, 256>>>((const float4*)x, n4);
        build_wt<<<dim3(KDIM / 32, QKV_N / 32), dim3(32, 8)>>>(wq, wk, wv);
        build_wot<<<dim3(KDIM / 32, C_DIM / 32), dim3(32, 8)>>>(wo);
    }

    cudaFuncSetAttribute(gemm_f16, cudaFuncAttributeMaxDynamicSharedMemorySize,
                         SMEM_BYTES);
    cudaFuncSetAttribute(gemm_f16, cudaFuncAttributePreferredSharedMemoryCarveout,
                         100);
    cudaFuncSetAttribute(fa_kernel, cudaFuncAttributeMaxDynamicSharedMemorySize,
                         FA_SMEM);
    cudaFuncSetAttribute(fa_kernel, cudaFuncAttributePreferredSharedMemoryCarveout,
                         100);

    // QKV projection (fused, rope in epilogue, fp16 outputs)
    gemm_f16<<<dim3(QKV_N / 128, T_SEQ / 128), 256, SMEM_BYTES>>>(XH, WH, nullptr,
                                                                  QKV_N, 1);

    // flash attention: one CTA per (128-query tile, head)
    fa_kernel<<<dim3(T_SEQ / 128, NH), 256, FA_SMEM>>>(QH, KH, VH);

    // output projection
    gemm_f16<<<dim3(C_DIM / 128, T_SEQ / 128), 256, SMEM_BYTES>>>(AOH, WOH, out,
                                                                  C_DIM, 0);
}

// round 15
// speedup vs baseline: 2.2858x; 1.0193x over previous
#include <cuda_runtime.h>
#include <cuda_fp16.h>
#include <math.h>
#include <stdint.h>

#define T_SEQ 4096
#define C_DIM 2048
#define KV_DIM 512
#define QKV_N 3072
#define NH 16
#define NKV 4
#define HD 128
#define HALF 64
#define WIN 64
#define KDIM 2048
#define KT 64                 // 2048 / 32

// Scratch (no runtime allocation allowed)
__device__ __half g_QH[T_SEQ * C_DIM];         // Q (roped), fp16
__device__ __half g_KH[T_SEQ * KV_DIM];        // K (roped), fp16
__device__ __half g_VH[T_SEQ * KV_DIM];        // V, fp16
__device__ __half g_AOH[T_SEQ * C_DIM];        // attention output, fp16
__device__ __half g_XH[T_SEQ * C_DIM];         // x, fp16
__device__ __half g_WH[QKV_N * KDIM];          // [wq|wk|wv]^T  [N][K] fp16
__device__ __half g_WOH[C_DIM * KDIM];         // wo^T          [N][K] fp16
__device__ float2 g_RC[T_SEQ * HALF];          // rope (cos,sin) table

// ---------------------------------------------------------------------------
// Fused one-time prep: rope table + x->fp16 + both weight transposes.
// Block ranges: [0,1024) rc | [1024,9216) x2h | [9216,15360) wt | rest wot.
// ---------------------------------------------------------------------------
#define NB_RC 1024
#define NB_X2H 8192
#define NB_WT 6144
#define NB_WOT 4096
#define NB_TOTAL (NB_RC + NB_X2H + NB_WT + NB_WOT)

__global__ void prep_kernel(const float4* __restrict__ x4,
                            const float* __restrict__ wq,
                            const float* __restrict__ wk,
                            const float* __restrict__ wv,
                            const float* __restrict__ wo) {
    __shared__ float tile[32][33];
    const int bid = blockIdx.x;
    const int tid = threadIdx.x;

    if (bid < NB_RC) {
        int idx = bid * 256 + tid;
        int t = idx >> 6;
        int j = idx & 63;
        float inv = powf(10000.0f, -(float)j / (float)HALF);
        float s, c;
        sincosf((float)t * inv, &s, &c);
        g_RC[idx] = make_float2(c, s);
    } else if (bid < NB_RC + NB_X2H) {
        int i = (bid - NB_RC) * 256 + tid;
        float4 v = x4[i];
        __half2* dst = (__half2*)(g_XH + (size_t)i * 4);
        dst[0] = __floats2half2_rn(v.x, v.y);
        dst[1] = __floats2half2_rn(v.z, v.w);
    } else if (bid < NB_RC + NB_X2H + NB_WT) {
        int bw = bid - NB_RC - NB_X2H;
        int k0 = (bw & 63) * 32;          // 64 k-blocks
        int n0 = (bw >> 6) * 32;          // 96 n-blocks
        int tx = tid & 31, ty = tid >> 5;
        const float* src;
        int nb, noff;
        if (n0 < C_DIM)               { src = wq; nb = C_DIM;  noff = 0; }
        else if (n0 < C_DIM + KV_DIM) { src = wk; nb = KV_DIM; noff = C_DIM; }
        else                          { src = wv; nb = KV_DIM; noff = C_DIM + KV_DIM; }
#pragma unroll
        for (int j = 0; j < 4; j++)
            tile[ty + j * 8][tx] =
                src[(size_t)(k0 + ty + j * 8) * nb + (n0 - noff + tx)];
        __syncthreads();
#pragma unroll
        for (int j = 0; j < 4; j++)
            g_WH[(size_t)(n0 + ty + j * 8) * KDIM + k0 + tx] =
                __float2half(tile[tx][ty + j * 8]);
    } else {
        int bw = bid - NB_RC - NB_X2H - NB_WT;
        int k0 = (bw & 63) * 32;
        int n0 = (bw >> 6) * 32;
        int tx = tid & 31, ty = tid >> 5;
#pragma unroll
        for (int j = 0; j < 4; j++)
            tile[ty + j * 8][tx] = wo[(size_t)(k0 + ty + j * 8) * C_DIM + n0 + tx];
        __syncthreads();
#pragma unroll
        for (int j = 0; j < 4; j++)
            g_WOH[(size_t)(n0 + ty + j * 8) * KDIM + k0 + tx] =
                __float2half(tile[tx][ty + j * 8]);
    }
}

// ---------------------------------------------------------------------------
// Shared MMA helpers
// ---------------------------------------------------------------------------
__device__ __forceinline__ void cp16(uint32_t dst, const __half* src) {
    asm volatile("cp.async.cg.shared.global [%0], [%1], 16;\n" :: "r"(dst), "l"(src));
}

#define LDSM4(r0, r1, r2, r3, addr)                                            \
    asm volatile("ldmatrix.sync.aligned.m8n8.x4.shared.b16 {%0,%1,%2,%3}, [%4];" \
                 : "=r"(r0), "=r"(r1), "=r"(r2), "=r"(r3) : "r"(addr))

#define LDSM4T(r0, r1, r2, r3, addr)                                           \
    asm volatile(                                                              \
        "ldmatrix.sync.aligned.m8n8.x4.trans.shared.b16 {%0,%1,%2,%3}, [%4];"  \
        : "=r"(r0), "=r"(r1), "=r"(r2), "=r"(r3) : "r"(addr))

__device__ __forceinline__ void mma_f16(float c[4], const uint32_t a[4],
                                        const uint32_t b[2]) {
    asm volatile(
        "mma.sync.aligned.m16n8k16.row.col.f32.f16.f16.f32 "
        "{%0,%1,%2,%3}, {%4,%5,%6,%7}, {%8,%9}, {%0,%1,%2,%3};\n"
        : "+f"(c[0]), "+f"(c[1]), "+f"(c[2]), "+f"(c[3])
        : "r"(a[0]), "r"(a[1]), "r"(a[2]), "r"(a[3]), "r"(b[0]), "r"(b[1]));
}

// ---------------------------------------------------------------------------
// FP16 mma.sync GEMM (round-10 config): CTA 128x128x32, 256 threads (2x4
// warps), warp tile 64x32, ldmatrix frags, K-major 40-half padded rows,
// cp.async 5-stage, 2 CTAs/SM.
// mode 0: plain fp32 store. mode 1: QKV epilogue (rope + route, fp16 out).
// ---------------------------------------------------------------------------
#define STAGES 5
#define SROW 40                               // halves per smem row
#define TILE_BYTES (128 * SROW * 2)           // 10240
#define STAGE_BYTES (2 * TILE_BYTES)          // 20480
#define SMEM_BYTES (STAGES * STAGE_BYTES)     // 102400

__device__ __forceinline__ void qkv_store(int t, int col, float v0, float v1) {
    if (col < C_DIM) {
        int jj = (col & 127) >> 1;
        float2 cs = g_RC[t * HALF + jj];
        *(__half2*)&g_QH[(size_t)t * C_DIM + col] =
            __floats2half2_rn(v0 * cs.x - v1 * cs.y, v0 * cs.y + v1 * cs.x);
    } else if (col < C_DIM + KV_DIM) {
        int kc = col - C_DIM;
        int jj = (kc & 127) >> 1;
        float2 cs = g_RC[t * HALF + jj];
        *(__half2*)&g_KH[(size_t)t * KV_DIM + kc] =
            __floats2half2_rn(v0 * cs.x - v1 * cs.y, v0 * cs.y + v1 * cs.x);
    } else {
        int vc = col - C_DIM - KV_DIM;
        *(__half2*)&g_VH[(size_t)t * KV_DIM + vc] = __floats2half2_rn(v0, v1);
    }
}

__global__ void __launch_bounds__(256, 2) gemm_f16(const __half* __restrict__ A,
                                                   const __half* __restrict__ Bt,
                                                   float* __restrict__ C,
                                                   int N, int mode) {
    extern __shared__ char smem[];
    uint32_t smem_u;
    asm("{.reg .u64 t; cvta.to.shared.u64 t, %1; cvt.u32.u64 %0, t;}"
        : "=r"(smem_u) : "l"(smem));

    const int tid = threadIdx.x;
    const int bm = blockIdx.y * 128;
    const int bn = blockIdx.x * 128;
    const int warp = tid >> 5;
    const int lane = tid & 31;
    const int wm = warp >> 2;
    const int wn = warp & 3;
    const int g  = lane >> 2;
    const int tg = lane & 3;

    const int mi = lane >> 3;
    const int rw = lane & 7;
    const uint32_t aoff0 =
        (uint32_t)(((wm * 64 + ((mi & 1) << 3) + rw) * SROW + ((mi >> 1) << 3)) * 2);
    const uint32_t boff0 =
        (uint32_t)(((wn * 32 + ((mi >> 1) << 3) + rw) * SROW + ((mi & 1) << 3)) * 2) +
        TILE_BYTES;

    const int row4 = tid >> 2;
    const int ch   = tid & 3;
    const __half* ap = A + (size_t)(bm + row4) * KDIM + ch * 8;
    const __half* bp = Bt + (size_t)(bn + row4) * KDIM + ch * 8;
    const uint32_t soff = (uint32_t)((row4 * SROW + ch * 8) * 2);

    float acc[4][4][4];
#pragma unroll
    for (int i = 0; i < 4; i++)
#pragma unroll
        for (int j = 0; j < 4; j++)
#pragma unroll
            for (int r = 0; r < 4; r++) acc[i][j][r] = 0.f;

#pragma unroll
    for (int s = 0; s < STAGES - 1; s++) {
        uint32_t base = smem_u + (uint32_t)s * STAGE_BYTES;
        cp16(base + soff, ap);
        cp16(base + soff + 64 * SROW * 2, ap + (size_t)64 * KDIM);
        cp16(base + TILE_BYTES + soff, bp);
        cp16(base + TILE_BYTES + soff + 64 * SROW * 2, bp + (size_t)64 * KDIM);
        asm volatile("cp.async.commit_group;\n" ::);
        ap += 32;
        bp += 32;
    }

    int st = 0;
    int wst = STAGES - 1;
    for (int kt = 0; kt < KT; kt++) {
        if (kt < KT - 3)
            asm volatile("cp.async.wait_group 3;\n" ::);
        else if (kt == KT - 3)
            asm volatile("cp.async.wait_group 2;\n" ::);
        else if (kt == KT - 2)
            asm volatile("cp.async.wait_group 1;\n" ::);
        else
            asm volatile("cp.async.wait_group 0;\n" ::);
        __syncthreads();

        if (kt + STAGES - 1 < KT) {
            uint32_t base = smem_u + (uint32_t)wst * STAGE_BYTES;
            cp16(base + soff, ap);
            cp16(base + soff + 64 * SROW * 2, ap + (size_t)64 * KDIM);
            cp16(base + TILE_BYTES + soff, bp);
            cp16(base + TILE_BYTES + soff + 64 * SROW * 2, bp + (size_t)64 * KDIM);
            asm volatile("cp.async.commit_group;\n" ::);
            ap += 32;
            bp += 32;
            wst = (wst == STAGES - 1) ? 0 : wst + 1;
        }

        const uint32_t sbase = smem_u + (uint32_t)st * STAGE_BYTES;
        st = (st == STAGES - 1) ? 0 : st + 1;

#pragma unroll
        for (int s = 0; s < 2; s++) {
            uint32_t af[4][4], bf[4][2];
#pragma unroll
            for (int i = 0; i < 4; i++)
                LDSM4(af[i][0], af[i][1], af[i][2], af[i][3],
                      sbase + aoff0 + (uint32_t)(i * 16 * SROW * 2 + s * 32));
#pragma unroll
            for (int jp = 0; jp < 2; jp++)
                LDSM4(bf[jp * 2][0], bf[jp * 2][1], bf[jp * 2 + 1][0],
                      bf[jp * 2 + 1][1],
                      sbase + boff0 + (uint32_t)(jp * 16 * SROW * 2 + s * 32));
#pragma unroll
            for (int i = 0; i < 4; i++)
#pragma unroll
                for (int j = 0; j < 4; j++) mma_f16(acc[i][j], af[i], bf[j]);
        }
    }

    if (mode == 0) {
#pragma unroll
        for (int i = 0; i < 4; i++)
#pragma unroll
            for (int j = 0; j < 4; j++) {
                int row = bm + wm * 64 + i * 16 + g;
                int col = bn + wn * 32 + j * 8 + 2 * tg;
                *(float2*)(C + (size_t)row * N + col) =
                    make_float2(acc[i][j][0], acc[i][j][1]);
                *(float2*)(C + (size_t)(row + 8) * N + col) =
                    make_float2(acc[i][j][2], acc[i][j][3]);
            }
    } else {
#pragma unroll
        for (int i = 0; i < 4; i++)
#pragma unroll
            for (int j = 0; j < 4; j++) {
                int row = bm + wm * 64 + i * 16 + g;
                int col = bn + wn * 32 + j * 8 + 2 * tg;
                qkv_store(row, col, acc[i][j][0], acc[i][j][1]);
                qkv_store(row + 8, col, acc[i][j][2], acc[i][j][3]);
            }
    }
}

// ---------------------------------------------------------------------------
// Flash-attention block kernel, 512 threads (16 warps -> 4 warps/SMSP).
// CTA = (128 queries, 1 head). Key window = 256 rows [t0-64, t0+191].
// S phase: warps 2x8, warp tile 64x32. P@V phase: warps 4x4, tile 32x32.
// Band mask in local coords: col in [row, row+128].
// ---------------------------------------------------------------------------
#define QROW 136                              // Q/K/V smem row, halves
#define PROW 264                              // P smem row, halves
#define OFF_Q 0
#define OFF_K 34816                           // 128*136*2
#define OFF_V 104448                          // OFF_K + 256*136*2
#define OFF_RED 174080                        // OFF_V + 256*136*2
#define FA_SMEM (OFF_RED + 8192)              // + pmax/psum ([8][128] each)

__global__ void __launch_bounds__(512, 1) fa_kernel(const __half* __restrict__ QH,
                                                    const __half* __restrict__ KH,
                                                    const __half* __restrict__ VH) {
    extern __shared__ char smem[];
    uint32_t su;
    asm("{.reg .u64 t; cvta.to.shared.u64 t, %1; cvt.u32.u64 %0, t;}"
        : "=r"(su) : "l"(smem));
    float* pmaxs = (float*)(smem + OFF_RED);          // [8][128]
    float* psums = (float*)(smem + OFF_RED + 4096);   // [8][128]

    const int tid = threadIdx.x;
    const int t0 = blockIdx.x * 128;
    const int h = blockIdx.y;
    const int kh = h >> 2;
    const int warp = tid >> 5;    // 0..15
    const int lane = tid & 31;
    const int g  = lane >> 2;
    const int tg = lane & 3;
    const int mi = lane >> 3;
    const int rw = lane & 7;
    const float scale = 0.08838834764831845f;  // 128^-0.5

    // ---- load Q (128x128) and K/V (256x128) fp16 tiles ----
    for (int c = tid; c < 2048; c += 512) {
        int row = c >> 4, o = c & 15;
        cp16(su + OFF_Q + row * (QROW * 2) + o * 16,
             QH + (size_t)(t0 + row) * C_DIM + h * HD + o * 8);
    }
    for (int c = tid; c < 4096; c += 512) {
        int row = c >> 4, o = c & 15;
        int s = t0 - 64 + row;
        uint32_t dk = su + OFF_K + row * (QROW * 2) + o * 16;
        uint32_t dv = su + OFF_V + row * (QROW * 2) + o * 16;
        if (s >= 0 && s < T_SEQ) {
            cp16(dk, KH + (size_t)s * KV_DIM + kh * HD + o * 8);
            cp16(dv, VH + (size_t)s * KV_DIM + kh * HD + o * 8);
        } else {
            *(uint4*)(smem + OFF_K + row * (QROW * 2) + o * 16) =
                make_uint4(0, 0, 0, 0);
            *(uint4*)(smem + OFF_V + row * (QROW * 2) + o * 16) =
                make_uint4(0, 0, 0, 0);
        }
    }
    asm volatile("cp.async.commit_group;\n" ::);
    asm volatile("cp.async.wait_group 0;\n" ::);
    __syncthreads();

    // ---- S = Q @ K^T : warps 2x8, warp tile 64x32, k=128 ----
    const int wmS = warp >> 3;    // 0..1
    const int wnS = warp & 7;     // 0..7
    const uint32_t aoffQ =
        su + OFF_Q +
        (uint32_t)(((wmS * 64 + ((mi & 1) << 3) + rw) * QROW + ((mi >> 1) << 3)) * 2);
    const uint32_t boffK =
        su + OFF_K +
        (uint32_t)(((wnS * 32 + ((mi >> 1) << 3) + rw) * QROW + ((mi & 1) << 3)) * 2);

    float acc[4][4][4];
#pragma unroll
    for (int i = 0; i < 4; i++)
#pragma unroll
        for (int j = 0; j < 4; j++)
#pragma unroll
            for (int r = 0; r < 4; r++) acc[i][j][r] = 0.f;

#pragma unroll
    for (int s = 0; s < 8; s++) {       // 8 k16 steps (k=128)
        uint32_t af[4][4], bf[4][2];
#pragma unroll
        for (int i = 0; i < 4; i++)
            LDSM4(af[i][0], af[i][1], af[i][2], af[i][3],
                  aoffQ + (uint32_t)(i * 16 * QROW * 2 + s * 32));
#pragma unroll
        for (int jp = 0; jp < 2; jp++)
            LDSM4(bf[jp * 2][0], bf[jp * 2][1], bf[jp * 2 + 1][0],
                  bf[jp * 2 + 1][1],
                  boffK + (uint32_t)(jp * 16 * QROW * 2 + s * 32));
#pragma unroll
        for (int i = 0; i < 4; i++)
#pragma unroll
            for (int j = 0; j < 4; j++) mma_f16(acc[i][j], af[i], bf[j]);
    }

    // ---- mask + scale + per-row max (warp-partial) ----
#pragma unroll
    for (int i = 0; i < 4; i++) {
#pragma unroll
        for (int rh = 0; rh < 2; rh++) {
            int row = wmS * 64 + i * 16 + g + rh * 8;
            float mx = -1e30f;
#pragma unroll
            for (int j = 0; j < 4; j++) {
#pragma unroll
                for (int rr = 0; rr < 2; rr++) {
                    int r = rh * 2 + rr;
                    int col = wnS * 32 + j * 8 + 2 * tg + rr;
                    int sK = t0 - 64 + col;
                    bool val = (col >= row) && (col <= row + 128) &&
                               (sK >= 0) && (sK < T_SEQ);
                    float v = val ? acc[i][j][r] * scale : -1e30f;
                    acc[i][j][r] = v;
                    mx = fmaxf(mx, v);
                }
            }
            mx = fmaxf(mx, __shfl_xor_sync(0xffffffffu, mx, 1));
            mx = fmaxf(mx, __shfl_xor_sync(0xffffffffu, mx, 2));
            if (tg == 0) pmaxs[wnS * 128 + row] = mx;
        }
    }
    __syncthreads();   // all warps done reading K; pmax complete

    // ---- exp + P (fp16, over K region) + per-row sum ----
#pragma unroll
    for (int i = 0; i < 4; i++) {
#pragma unroll
        for (int rh = 0; rh < 2; rh++) {
            int row = wmS * 64 + i * 16 + g + rh * 8;
            float mrow = -1e30f;
#pragma unroll
            for (int q = 0; q < 8; q++) mrow = fmaxf(mrow, pmaxs[q * 128 + row]);
            float sm = 0.f;
#pragma unroll
            for (int j = 0; j < 4; j++) {
                int r = rh * 2;
                float v0 = acc[i][j][r], v1 = acc[i][j][r + 1];
                float p0 = (v0 > -1e29f) ? __expf(v0 - mrow) : 0.f;
                float p1 = (v1 > -1e29f) ? __expf(v1 - mrow) : 0.f;
                sm += p0 + p1;
                int col = wnS * 32 + j * 8 + 2 * tg;
                *(__half2*)(smem + OFF_K + row * (PROW * 2) + col * 2) =
                    __floats2half2_rn(p0, p1);
            }
            sm += __shfl_xor_sync(0xffffffffu, sm, 1);
            sm += __shfl_xor_sync(0xffffffffu, sm, 2);
            if (tg == 0) psums[wnS * 128 + row] = sm;
        }
    }
    __syncthreads();   // P + psums complete

    // ---- O = P @ V : warps 4x4, warp tile 32x32, k=256 ----
    const int wmO = warp >> 2;    // 0..3
    const int wnO = warp & 3;     // 0..3
    const uint32_t aoffP =
        su + OFF_K +
        (uint32_t)(((wmO * 32 + ((mi & 1) << 3) + rw) * PROW + ((mi >> 1) << 3)) * 2);
    const uint32_t voff =
        su + OFF_V +
        (uint32_t)((((mi & 1) * 8 + rw) * QROW + wnO * 32 + ((mi >> 1) << 3)) * 2);

    float oacc[2][4][4];
#pragma unroll
    for (int i = 0; i < 2; i++)
#pragma unroll
        for (int j = 0; j < 4; j++)
#pragma unroll
            for (int r = 0; r < 4; r++) oacc[i][j][r] = 0.f;

#pragma unroll
    for (int ks = 0; ks < 16; ks++) {   // 16 k16 steps (k=256)
        uint32_t af[2][4], bf[4][2];
#pragma unroll
        for (int i = 0; i < 2; i++)
            LDSM4(af[i][0], af[i][1], af[i][2], af[i][3],
                  aoffP + (uint32_t)(i * 16 * PROW * 2 + ks * 32));
        LDSM4T(bf[0][0], bf[0][1], bf[1][0], bf[1][1],
               voff + (uint32_t)(ks * 16 * QROW * 2));
        LDSM4T(bf[2][0], bf[2][1], bf[3][0], bf[3][1],
               voff + 32 + (uint32_t)(ks * 16 * QROW * 2));
#pragma unroll
        for (int i = 0; i < 2; i++)
#pragma unroll
            for (int j = 0; j < 4; j++) mma_f16(oacc[i][j], af[i], bf[j]);
    }

    // ---- normalize + store fp16 ----
#pragma unroll
    for (int i = 0; i < 2; i++) {
        float li[2];
#pragma unroll
        for (int rh = 0; rh < 2; rh++) {
            int row = wmO * 32 + i * 16 + g + rh * 8;
            float l = 0.f;
#pragma unroll
            for (int q = 0; q < 8; q++) l += psums[q * 128 + row];
            li[rh] = 1.f / l;
        }
#pragma unroll
        for (int j = 0; j < 4; j++) {
            int row = wmO * 32 + i * 16 + g;
            int col = wnO * 32 + j * 8 + 2 * tg;
            *(__half2*)(g_AOH + (size_t)(t0 + row) * C_DIM + h * HD + col) =
                __floats2half2_rn(oacc[i][j][0] * li[0], oacc[i][j][1] * li[0]);
            *(__half2*)(g_AOH + (size_t)(t0 + row + 8) * C_DIM + h * HD + col) =
                __floats2half2_rn(oacc[i][j][2] * li[1], oacc[i][j][3] * li[1]);
        }
    }
}

// ---------------------------------------------------------------------------
extern "C" void kernel_launch(void* const* d_in, const int* in_sizes, int n_in,
                              void* d_out, int out_size) {
    const float* x  = (const float*)d_in[0];
    const float* wq = (const float*)d_in[1];
    const float* wk = (const float*)d_in[2];
    const float* wv = (const float*)d_in[3];
    const float* wo = (const float*)d_in[4];
    // d_in[5] = sink: constant per softmax row -> cancels; ignored.
    float* out = (float*)d_out;

    __half *QH, *KH, *VH, *XH, *WH, *WOH, *AOH;
    cudaGetSymbolAddress((void**)&QH,  g_QH);
    cudaGetSymbolAddress((void**)&KH,  g_KH);
    cudaGetSymbolAddress((void**)&VH,  g_VH);
    cudaGetSymbolAddress((void**)&XH,  g_XH);
    cudaGetSymbolAddress((void**)&WH,  g_WH);
    cudaGetSymbolAddress((void**)&WOH, g_WOH);
    cudaGetSymbolAddress((void**)&AOH, g_AOH);

    // one-time prep (single fused launch)
    prep_kernel<<<NB_TOTAL, 256>>>((const float4*)x, wq, wk, wv, wo);

    cudaFuncSetAttribute(gemm_f16, cudaFuncAttributeMaxDynamicSharedMemorySize,
                         SMEM_BYTES);
    cudaFuncSetAttribute(gemm_f16, cudaFuncAttributePreferredSharedMemoryCarveout,
                         100);
    cudaFuncSetAttribute(fa_kernel, cudaFuncAttributeMaxDynamicSharedMemorySize,
                         FA_SMEM);
    cudaFuncSetAttribute(fa_kernel, cudaFuncAttributePreferredSharedMemoryCarveout,
                         100);

    // QKV projection (fused, rope in epilogue, fp16 outputs)
    gemm_f16<<<dim3(QKV_N / 128, T_SEQ / 128), 256, SMEM_BYTES>>>(XH, WH, nullptr,
                                                                  QKV_N, 1);

    // flash attention: one CTA per (128-query tile, head), 512 threads
    fa_kernel<<<dim3(T_SEQ / 128, NH), 512, FA_SMEM>>>(QH, KH, VH);

    // output projection
    gemm_f16<<<dim3(C_DIM / 128, T_SEQ / 128), 256, SMEM_BYTES>>>(AOH, WOH, out,
                                                                  C_DIM, 0);
}

// round 17
// speedup vs baseline: 2.3833x; 1.0427x over previous
#include <cuda_runtime.h>
#include <cuda_fp16.h>
#include <math.h>
#include <stdint.h>

#define T_SEQ 4096
#define C_DIM 2048
#define KV_DIM 512
#define QKV_N 3072
#define NH 16
#define NKV 4
#define HD 128
#define HALF 64
#define WIN 64
#define KDIM 2048
#define KT 64                 // 2048 / 32

// Scratch (no runtime allocation allowed)
__device__ __half g_QH[T_SEQ * C_DIM];         // Q (roped), fp16
__device__ __half g_KH[T_SEQ * KV_DIM];        // K (roped), fp16
__device__ __half g_VH[T_SEQ * KV_DIM];        // V, fp16
__device__ __half g_AOH[T_SEQ * C_DIM];        // attention output, fp16
__device__ __half g_XH[T_SEQ * C_DIM];         // x, fp16
__device__ __half g_WH[QKV_N * KDIM];          // [wq|wk|wv]^T  [N][K] fp16
__device__ __half g_WOH[C_DIM * KDIM];         // wo^T          [N][K] fp16
__device__ float2 g_RC[T_SEQ * HALF];          // rope (cos,sin) table

// ---------------------------------------------------------------------------
// Fused one-time prep: rope table + x->fp16 + both weight transposes.
// ---------------------------------------------------------------------------
#define NB_RC 1024
#define NB_X2H 8192
#define NB_WT 6144
#define NB_WOT 4096
#define NB_TOTAL (NB_RC + NB_X2H + NB_WT + NB_WOT)

__global__ void prep_kernel(const float4* __restrict__ x4,
                            const float* __restrict__ wq,
                            const float* __restrict__ wk,
                            const float* __restrict__ wv,
                            const float* __restrict__ wo) {
    __shared__ float tile[32][33];
    const int bid = blockIdx.x;
    const int tid = threadIdx.x;

    if (bid < NB_RC) {
        int idx = bid * 256 + tid;
        int t = idx >> 6;
        int j = idx & 63;
        float inv = powf(10000.0f, -(float)j / (float)HALF);
        float s, c;
        sincosf((float)t * inv, &s, &c);
        g_RC[idx] = make_float2(c, s);
    } else if (bid < NB_RC + NB_X2H) {
        int i = (bid - NB_RC) * 256 + tid;
        float4 v = x4[i];
        __half2* dst = (__half2*)(g_XH + (size_t)i * 4);
        dst[0] = __floats2half2_rn(v.x, v.y);
        dst[1] = __floats2half2_rn(v.z, v.w);
    } else if (bid < NB_RC + NB_X2H + NB_WT) {
        int bw = bid - NB_RC - NB_X2H;
        int k0 = (bw & 63) * 32;
        int n0 = (bw >> 6) * 32;
        int tx = tid & 31, ty = tid >> 5;
        const float* src;
        int nb, noff;
        if (n0 < C_DIM)               { src = wq; nb = C_DIM;  noff = 0; }
        else if (n0 < C_DIM + KV_DIM) { src = wk; nb = KV_DIM; noff = C_DIM; }
        else                          { src = wv; nb = KV_DIM; noff = C_DIM + KV_DIM; }
#pragma unroll
        for (int j = 0; j < 4; j++)
            tile[ty + j * 8][tx] =
                src[(size_t)(k0 + ty + j * 8) * nb + (n0 - noff + tx)];
        __syncthreads();
#pragma unroll
        for (int j = 0; j < 4; j++)
            g_WH[(size_t)(n0 + ty + j * 8) * KDIM + k0 + tx] =
                __float2half(tile[tx][ty + j * 8]);
    } else {
        int bw = bid - NB_RC - NB_X2H - NB_WT;
        int k0 = (bw & 63) * 32;
        int n0 = (bw >> 6) * 32;
        int tx = tid & 31, ty = tid >> 5;
#pragma unroll
        for (int j = 0; j < 4; j++)
            tile[ty + j * 8][tx] = wo[(size_t)(k0 + ty + j * 8) * C_DIM + n0 + tx];
        __syncthreads();
#pragma unroll
        for (int j = 0; j < 4; j++)
            g_WOH[(size_t)(n0 + ty + j * 8) * KDIM + k0 + tx] =
                __float2half(tile[tx][ty + j * 8]);
    }
}

// ---------------------------------------------------------------------------
// Shared MMA helpers
// ---------------------------------------------------------------------------
__device__ __forceinline__ void cp16(uint32_t dst, const __half* src) {
    asm volatile("cp.async.cg.shared.global [%0], [%1], 16;\n" :: "r"(dst), "l"(src));
}

#define LDSM4(r0, r1, r2, r3, addr)                                            \
    asm volatile("ldmatrix.sync.aligned.m8n8.x4.shared.b16 {%0,%1,%2,%3}, [%4];" \
                 : "=r"(r0), "=r"(r1), "=r"(r2), "=r"(r3) : "r"(addr))

#define LDSM4T(r0, r1, r2, r3, addr)                                           \
    asm volatile(                                                              \
        "ldmatrix.sync.aligned.m8n8.x4.trans.shared.b16 {%0,%1,%2,%3}, [%4];"  \
        : "=r"(r0), "=r"(r1), "=r"(r2), "=r"(r3) : "r"(addr))

__device__ __forceinline__ void mma_f16(float c[4], const uint32_t a[4],
                                        const uint32_t b[2]) {
    asm volatile(
        "mma.sync.aligned.m16n8k16.row.col.f32.f16.f16.f32 "
        "{%0,%1,%2,%3}, {%4,%5,%6,%7}, {%8,%9}, {%0,%1,%2,%3};\n"
        : "+f"(c[0]), "+f"(c[1]), "+f"(c[2]), "+f"(c[3])
        : "r"(a[0]), "r"(a[1]), "r"(a[2]), "r"(a[3]), "r"(b[0]), "r"(b[1]));
}

// ---------------------------------------------------------------------------
// FP16 mma.sync GEMM: CTA 128x128x32, 256 threads (2x4 warps), warp tile
// 64x32, ldmatrix frags, K-major 40-half padded rows, 5-stage cp.async ring,
// 2 tiles per barrier window: wait_group covers BOTH tiles before the
// barrier, so every thread's cp.async data for both tiles is resident at the
// barrier (fixes the per-thread-group visibility race). 2 CTAs/SM.
// mode 0: plain fp32 store. mode 1: QKV epilogue (rope + route, fp16 out).
// ---------------------------------------------------------------------------
#define STAGES 5
#define SROW 40                               // halves per smem row
#define TILE_BYTES (128 * SROW * 2)           // 10240
#define STAGE_BYTES (2 * TILE_BYTES)          // 20480
#define SMEM_BYTES (STAGES * STAGE_BYTES)     // 102400

__device__ __forceinline__ void qkv_store(int t, int col, float v0, float v1) {
    if (col < C_DIM) {
        int jj = (col & 127) >> 1;
        float2 cs = g_RC[t * HALF + jj];
        *(__half2*)&g_QH[(size_t)t * C_DIM + col] =
            __floats2half2_rn(v0 * cs.x - v1 * cs.y, v0 * cs.y + v1 * cs.x);
    } else if (col < C_DIM + KV_DIM) {
        int kc = col - C_DIM;
        int jj = (kc & 127) >> 1;
        float2 cs = g_RC[t * HALF + jj];
        *(__half2*)&g_KH[(size_t)t * KV_DIM + kc] =
            __floats2half2_rn(v0 * cs.x - v1 * cs.y, v0 * cs.y + v1 * cs.x);
    } else {
        int vc = col - C_DIM - KV_DIM;
        *(__half2*)&g_VH[(size_t)t * KV_DIM + vc] = __floats2half2_rn(v0, v1);
    }
}

__global__ void __launch_bounds__(256, 2) gemm_f16(const __half* __restrict__ A,
                                                   const __half* __restrict__ Bt,
                                                   float* __restrict__ C,
                                                   int N, int mode) {
    extern __shared__ char smem[];
    uint32_t smem_u;
    asm("{.reg .u64 t; cvta.to.shared.u64 t, %1; cvt.u32.u64 %0, t;}"
        : "=r"(smem_u) : "l"(smem));

    const int tid = threadIdx.x;
    const int bm = blockIdx.y * 128;
    const int bn = blockIdx.x * 128;
    const int warp = tid >> 5;
    const int lane = tid & 31;
    const int wm = warp >> 2;
    const int wn = warp & 3;
    const int g  = lane >> 2;
    const int tg = lane & 3;

    const int mi = lane >> 3;
    const int rw = lane & 7;
    const uint32_t aoff0 =
        (uint32_t)(((wm * 64 + ((mi & 1) << 3) + rw) * SROW + ((mi >> 1) << 3)) * 2);
    const uint32_t boff0 =
        (uint32_t)(((wn * 32 + ((mi >> 1) << 3) + rw) * SROW + ((mi & 1) << 3)) * 2) +
        TILE_BYTES;

    const int row4 = tid >> 2;
    const int ch   = tid & 3;
    const __half* ap = A + (size_t)(bm + row4) * KDIM + ch * 8;
    const __half* bp = Bt + (size_t)(bn + row4) * KDIM + ch * 8;
    const uint32_t soff = (uint32_t)((row4 * SROW + ch * 8) * 2);

    float acc[4][4][4];
#pragma unroll
    for (int i = 0; i < 4; i++)
#pragma unroll
        for (int j = 0; j < 4; j++)
#pragma unroll
            for (int r = 0; r < 4; r++) acc[i][j][r] = 0.f;

    // prologue: tiles 0,1,2 into stages 0,1,2
#pragma unroll
    for (int s = 0; s < 3; s++) {
        uint32_t base = smem_u + (uint32_t)s * STAGE_BYTES;
        cp16(base + soff, ap);
        cp16(base + soff + 64 * SROW * 2, ap + (size_t)64 * KDIM);
        cp16(base + TILE_BYTES + soff, bp);
        cp16(base + TILE_BYTES + soff + 64 * SROW * 2, bp + (size_t)64 * KDIM);
        asm volatile("cp.async.commit_group;\n" ::);
        ap += 32;
        bp += 32;
    }

    int st = 0;          // consume stage
    int wst = 3;         // write stage (next tile = 3)
    for (int kt2 = 0; kt2 < KT; kt2 += 2) {
        // own groups for tiles kt2 and kt2+1 must be complete
        // (pending afterwards: only tile kt2+2, if committed)
        if (kt2 + 2 < KT)
            asm volatile("cp.async.wait_group 1;\n" ::);
        else
            asm volatile("cp.async.wait_group 0;\n" ::);
        __syncthreads();   // now ALL threads' data for both tiles is resident

        // prefetch tiles kt2+3, kt2+4
#pragma unroll
        for (int p = 0; p < 2; p++) {
            if (kt2 + 3 + p < KT) {
                uint32_t base = smem_u + (uint32_t)wst * STAGE_BYTES;
                cp16(base + soff, ap);
                cp16(base + soff + 64 * SROW * 2, ap + (size_t)64 * KDIM);
                cp16(base + TILE_BYTES + soff, bp);
                cp16(base + TILE_BYTES + soff + 64 * SROW * 2,
                     bp + (size_t)64 * KDIM);
                asm volatile("cp.async.commit_group;\n" ::);
                ap += 32;
                bp += 32;
                wst = (wst == STAGES - 1) ? 0 : wst + 1;
            }
        }

        // compute tiles kt2 and kt2+1
#pragma unroll
        for (int u = 0; u < 2; u++) {
            const uint32_t sbase = smem_u + (uint32_t)st * STAGE_BYTES;
            st = (st == STAGES - 1) ? 0 : st + 1;
#pragma unroll
            for (int s = 0; s < 2; s++) {
                uint32_t af[4][4], bf[4][2];
#pragma unroll
                for (int i = 0; i < 4; i++)
                    LDSM4(af[i][0], af[i][1], af[i][2], af[i][3],
                          sbase + aoff0 + (uint32_t)(i * 16 * SROW * 2 + s * 32));
#pragma unroll
                for (int jp = 0; jp < 2; jp++)
                    LDSM4(bf[jp * 2][0], bf[jp * 2][1], bf[jp * 2 + 1][0],
                          bf[jp * 2 + 1][1],
                          sbase + boff0 + (uint32_t)(jp * 16 * SROW * 2 + s * 32));
#pragma unroll
                for (int i = 0; i < 4; i++)
#pragma unroll
                    for (int j = 0; j < 4; j++) mma_f16(acc[i][j], af[i], bf[j]);
            }
        }
    }

    if (mode == 0) {
#pragma unroll
        for (int i = 0; i < 4; i++)
#pragma unroll
            for (int j = 0; j < 4; j++) {
                int row = bm + wm * 64 + i * 16 + g;
                int col = bn + wn * 32 + j * 8 + 2 * tg;
                *(float2*)(C + (size_t)row * N + col) =
                    make_float2(acc[i][j][0], acc[i][j][1]);
                *(float2*)(C + (size_t)(row + 8) * N + col) =
                    make_float2(acc[i][j][2], acc[i][j][3]);
            }
    } else {
#pragma unroll
        for (int i = 0; i < 4; i++)
#pragma unroll
            for (int j = 0; j < 4; j++) {
                int row = bm + wm * 64 + i * 16 + g;
                int col = bn + wn * 32 + j * 8 + 2 * tg;
                qkv_store(row, col, acc[i][j][0], acc[i][j][1]);
                qkv_store(row + 8, col, acc[i][j][2], acc[i][j][3]);
            }
    }
}

// ---------------------------------------------------------------------------
// Flash-attention block kernel, 512 threads (16 warps -> 4 warps/SMSP).
// CTA = (128 queries, 1 head). Key window = 256 rows [t0-64, t0+191].
// S phase: warps 2x8, warp tile 64x32. P@V phase: warps 4x4, tile 32x32.
// Band mask in local coords: col in [row, row+128].
// ---------------------------------------------------------------------------
#define QROW 136                              // Q/K/V smem row, halves
#define PROW 264                              // P smem row, halves
#define OFF_Q 0
#define OFF_K 34816                           // 128*136*2
#define OFF_V 104448                          // OFF_K + 256*136*2
#define OFF_RED 174080                        // OFF_V + 256*136*2
#define FA_SMEM (OFF_RED + 8192)              // + pmax/psum ([8][128] each)

__global__ void __launch_bounds__(512, 1) fa_kernel(const __half* __restrict__ QH,
                                                    const __half* __restrict__ KH,
                                                    const __half* __restrict__ VH) {
    extern __shared__ char smem[];
    uint32_t su;
    asm("{.reg .u64 t; cvta.to.shared.u64 t, %1; cvt.u32.u64 %0, t;}"
        : "=r"(su) : "l"(smem));
    float* pmaxs = (float*)(smem + OFF_RED);          // [8][128]
    float* psums = (float*)(smem + OFF_RED + 4096);   // [8][128]

    const int tid = threadIdx.x;
    const int t0 = blockIdx.x * 128;
    const int h = blockIdx.y;
    const int kh = h >> 2;
    const int warp = tid >> 5;    // 0..15
    const int lane = tid & 31;
    const int g  = lane >> 2;
    const int tg = lane & 3;
    const int mi = lane >> 3;
    const int rw = lane & 7;
    const float scale = 0.08838834764831845f;  // 128^-0.5

    // ---- load Q (128x128) and K/V (256x128) fp16 tiles ----
    for (int c = tid; c < 2048; c += 512) {
        int row = c >> 4, o = c & 15;
        cp16(su + OFF_Q + row * (QROW * 2) + o * 16,
             QH + (size_t)(t0 + row) * C_DIM + h * HD + o * 8);
    }
    for (int c = tid; c < 4096; c += 512) {
        int row = c >> 4, o = c & 15;
        int s = t0 - 64 + row;
        uint32_t dk = su + OFF_K + row * (QROW * 2) + o * 16;
        uint32_t dv = su + OFF_V + row * (QROW * 2) + o * 16;
        if (s >= 0 && s < T_SEQ) {
            cp16(dk, KH + (size_t)s * KV_DIM + kh * HD + o * 8);
            cp16(dv, VH + (size_t)s * KV_DIM + kh * HD + o * 8);
        } else {
            *(uint4*)(smem + OFF_K + row * (QROW * 2) + o * 16) =
                make_uint4(0, 0, 0, 0);
            *(uint4*)(smem + OFF_V + row * (QROW * 2) + o * 16) =
                make_uint4(0, 0, 0, 0);
        }
    }
    asm volatile("cp.async.commit_group;\n" ::);
    asm volatile("cp.async.wait_group 0;\n" ::);
    __syncthreads();

    // ---- S = Q @ K^T : warps 2x8, warp tile 64x32, k=128 ----
    const int wmS = warp >> 3;    // 0..1
    const int wnS = warp & 7;     // 0..7
    const uint32_t aoffQ =
        su + OFF_Q +
        (uint32_t)(((wmS * 64 + ((mi & 1) << 3) + rw) * QROW + ((mi >> 1) << 3)) * 2);
    const uint32_t boffK =
        su + OFF_K +
        (uint32_t)(((wnS * 32 + ((mi >> 1) << 3) + rw) * QROW + ((mi & 1) << 3)) * 2);

    float acc[4][4][4];
#pragma unroll
    for (int i = 0; i < 4; i++)
#pragma unroll
        for (int j = 0; j < 4; j++)
#pragma unroll
            for (int r = 0; r < 4; r++) acc[i][j][r] = 0.f;

#pragma unroll
    for (int s = 0; s < 8; s++) {       // 8 k16 steps (k=128)
        uint32_t af[4][4], bf[4][2];
#pragma unroll
        for (int i = 0; i < 4; i++)
            LDSM4(af[i][0], af[i][1], af[i][2], af[i][3],
                  aoffQ + (uint32_t)(i * 16 * QROW * 2 + s * 32));
#pragma unroll
        for (int jp = 0; jp < 2; jp++)
            LDSM4(bf[jp * 2][0], bf[jp * 2][1], bf[jp * 2 + 1][0],
                  bf[jp * 2 + 1][1],
                  boffK + (uint32_t)(jp * 16 * QROW * 2 + s * 32));
#pragma unroll
        for (int i = 0; i < 4; i++)
#pragma unroll
            for (int j = 0; j < 4; j++) mma_f16(acc[i][j], af[i], bf[j]);
    }

    // ---- mask + scale + per-row max (warp-partial) ----
#pragma unroll
    for (int i = 0; i < 4; i++) {
#pragma unroll
        for (int rh = 0; rh < 2; rh++) {
            int row = wmS * 64 + i * 16 + g + rh * 8;
            float mx = -1e30f;
#pragma unroll
            for (int j = 0; j < 4; j++) {
#pragma unroll
                for (int rr = 0; rr < 2; rr++) {
                    int r = rh * 2 + rr;
                    int col = wnS * 32 + j * 8 + 2 * tg + rr;
                    int sK = t0 - 64 + col;
                    bool val = (col >= row) && (col <= row + 128) &&
                               (sK >= 0) && (sK < T_SEQ);
                    float v = val ? acc[i][j][r] * scale : -1e30f;
                    acc[i][j][r] = v;
                    mx = fmaxf(mx, v);
                }
            }
            mx = fmaxf(mx, __shfl_xor_sync(0xffffffffu, mx, 1));
            mx = fmaxf(mx, __shfl_xor_sync(0xffffffffu, mx, 2));
            if (tg == 0) pmaxs[wnS * 128 + row] = mx;
        }
    }
    __syncthreads();   // all warps done reading K; pmax complete

    // ---- exp + P (fp16, over K region) + per-row sum ----
#pragma unroll
    for (int i = 0; i < 4; i++) {
#pragma unroll
        for (int rh = 0; rh < 2; rh++) {
            int row = wmS * 64 + i * 16 + g + rh * 8;
            float mrow = -1e30f;
#pragma unroll
            for (int q = 0; q < 8; q++) mrow = fmaxf(mrow, pmaxs[q * 128 + row]);
            float sm = 0.f;
#pragma unroll
            for (int j = 0; j < 4; j++) {
                int r = rh * 2;
                float v0 = acc[i][j][r], v1 = acc[i][j][r + 1];
                float p0 = (v0 > -1e29f) ? __expf(v0 - mrow) : 0.f;
                float p1 = (v1 > -1e29f) ? __expf(v1 - mrow) : 0.f;
                sm += p0 + p1;
                int col = wnS * 32 + j * 8 + 2 * tg;
                *(__half2*)(smem + OFF_K + row * (PROW * 2) + col * 2) =
                    __floats2half2_rn(p0, p1);
            }
            sm += __shfl_xor_sync(0xffffffffu, sm, 1);
            sm += __shfl_xor_sync(0xffffffffu, sm, 2);
            if (tg == 0) psums[wnS * 128 + row] = sm;
        }
    }
    __syncthreads();   // P + psums complete

    // ---- O = P @ V : warps 4x4, warp tile 32x32, k=256 ----
    const int wmO = warp >> 2;    // 0..3
    const int wnO = warp & 3;     // 0..3
    const uint32_t aoffP =
        su + OFF_K +
        (uint32_t)(((wmO * 32 + ((mi & 1) << 3) + rw) * PROW + ((mi >> 1) << 3)) * 2);
    const uint32_t voff =
        su + OFF_V +
        (uint32_t)((((mi & 1) * 8 + rw) * QROW + wnO * 32 + ((mi >> 1) << 3)) * 2);

    float oacc[2][4][4];
#pragma unroll
    for (int i = 0; i < 2; i++)
#pragma unroll
        for (int j = 0; j < 4; j++)
#pragma unroll
            for (int r = 0; r < 4; r++) oacc[i][j][r] = 0.f;

#pragma unroll
    for (int ks = 0; ks < 16; ks++) {   // 16 k16 steps (k=256)
        uint32_t af[2][4], bf[4][2];
#pragma unroll
        for (int i = 0; i < 2; i++)
            LDSM4(af[i][0], af[i][1], af[i][2], af[i][3],
                  aoffP + (uint32_t)(i * 16 * PROW * 2 + ks * 32));
        LDSM4T(bf[0][0], bf[0][1], bf[1][0], bf[1][1],
               voff + (uint32_t)(ks * 16 * QROW * 2));
        LDSM4T(bf[2][0], bf[2][1], bf[3][0], bf[3][1],
               voff + 32 + (uint32_t)(ks * 16 * QROW * 2));
#pragma unroll
        for (int i = 0; i < 2; i++)
#pragma unroll
            for (int j = 0; j < 4; j++) mma_f16(oacc[i][j], af[i], bf[j]);
    }

    // ---- normalize + store fp16 ----
#pragma unroll
    for (int i = 0; i < 2; i++) {
        float li[2];
#pragma unroll
        for (int rh = 0; rh < 2; rh++) {
            int row = wmO * 32 + i * 16 + g + rh * 8;
            float l = 0.f;
#pragma unroll
            for (int q = 0; q < 8; q++) l += psums[q * 128 + row];
            li[rh] = 1.f / l;
        }
#pragma unroll
        for (int j = 0; j < 4; j++) {
            int row = wmO * 32 + i * 16 + g;
            int col = wnO * 32 + j * 8 + 2 * tg;
            *(__half2*)(g_AOH + (size_t)(t0 + row) * C_DIM + h * HD + col) =
                __floats2half2_rn(oacc[i][j][0] * li[0], oacc[i][j][1] * li[0]);
            *(__half2*)(g_AOH + (size_t)(t0 + row + 8) * C_DIM + h * HD + col) =
                __floats2half2_rn(oacc[i][j][2] * li[1], oacc[i][j][3] * li[1]);
        }
    }
}

// ---------------------------------------------------------------------------
extern "C" void kernel_launch(void* const* d_in, const int* in_sizes, int n_in,
                              void* d_out, int out_size) {
    const float* x  = (const float*)d_in[0];
    const float* wq = (const float*)d_in[1];
    const float* wk = (const float*)d_in[2];
    const float* wv = (const float*)d_in[3];
    const float* wo = (const float*)d_in[4];
    // d_in[5] = sink: constant per softmax row -> cancels; ignored.
    float* out = (float*)d_out;

    __half *QH, *KH, *VH, *XH, *WH, *WOH, *AOH;
    cudaGetSymbolAddress((void**)&QH,  g_QH);
    cudaGetSymbolAddress((void**)&KH,  g_KH);
    cudaGetSymbolAddress((void**)&VH,  g_VH);
    cudaGetSymbolAddress((void**)&XH,  g_XH);
    cudaGetSymbolAddress((void**)&WH,  g_WH);
    cudaGetSymbolAddress((void**)&WOH, g_WOH);
    cudaGetSymbolAddress((void**)&AOH, g_AOH);

    // one-time prep (single fused launch)
    prep_kernel<<<NB_TOTAL, 256>>>((const float4*)x, wq, wk, wv, wo);

    cudaFuncSetAttribute(gemm_f16, cudaFuncAttributeMaxDynamicSharedMemorySize,
                         SMEM_BYTES);
    cudaFuncSetAttribute(gemm_f16, cudaFuncAttributePreferredSharedMemoryCarveout,
                         100);
    cudaFuncSetAttribute(fa_kernel, cudaFuncAttributeMaxDynamicSharedMemorySize,
                         FA_SMEM);
    cudaFuncSetAttribute(fa_kernel, cudaFuncAttributePreferredSharedMemoryCarveout,
                         100);

    // QKV projection (fused, rope in epilogue, fp16 outputs)
    gemm_f16<<<dim3(QKV_N / 128, T_SEQ / 128), 256, SMEM_BYTES>>>(XH, WH, nullptr,
                                                                  QKV_N, 1);

    // flash attention: one CTA per (128-query tile, head), 512 threads
    fa_kernel<<<dim3(T_SEQ / 128, NH), 512, FA_SMEM>>>(QH, KH, VH);

    // output projection
    gemm_f16<<<dim3(C_DIM / 128, T_SEQ / 128), 256, SMEM_BYTES>>>(AOH, WOH, out,
                                                                  C_DIM, 0);
}